// round 8
// baseline (speedup 1.0000x reference)
#include <cuda_runtime.h>
#include <cuda_fp16.h>
#include <math.h>

#define BATCH 4
#define S 160
#define SS (S*S)
#define VOX (S*S*S)
#define TOT (BATCH*VOX)

#define NB12 1280  // 4 batch x 160 d x 2 h-halves
#define NB3  1280  // 4 chunks x 4 batch x 80 h-pairs

// 1D Gaussian taps exp(-t^2/50), t=-4..4
__constant__ float KW[9] = {
  0.72614902f, 0.83527023f, 0.92311633f, 0.98019868f, 1.0f,
  0.98019868f, 0.92311633f, 0.83527023f, 0.72614902f
};
#define KSUM1 7.92946854f
// prefix sums of first n taps (for edge-clipped kernel sums)
__constant__ float KPRE[5] = {0.f, 0.72614902f, 1.56141925f, 2.48453558f, 3.46473426f};

__device__ __half  g_t2[TOT];          // conv-W-H of labels (fp16)
__device__ double  g_p1[NB12][3];      // per-block partials: p, x, x*p
__device__ float   g_mean[2][BATCH];   // class means
__device__ double  g_p3[NB3][4];       // per-block partials: n0, d0, n1, d1
__device__ unsigned int g_cnt12;       // zero-init; reset by last block
__device__ unsigned int g_cnt3;

__device__ __forceinline__ float esum(int c){
  int lo = 4 - c;   if (lo < 0) lo = 0;
  int hi = c - 155; if (hi < 0) hi = 0;
  return KSUM1 - KPRE[lo] - KPRE[hi];
}

__device__ __forceinline__ double blockReduce160(double v, double* sm){
  int t = threadIdx.x;
  sm[t] = v;
  __syncthreads();
  if (t < 32){
    double s = sm[t] + sm[t+32] + sm[t+64] + sm[t+96] + sm[t+128];
    #pragma unroll
    for (int o = 16; o > 0; o >>= 1) s += __shfl_down_sync(0xffffffffu, s, o);
    if (t == 0) sm[0] = s;
  }
  __syncthreads();
  double r = sm[0];
  __syncthreads();
  return r;
}

__device__ __forceinline__ double blockReduce320(double v, double* sm){
  int t = threadIdx.x;
  sm[t] = v;
  __syncthreads();
  if (t < 32){
    double s = 0.0;
    #pragma unroll
    for (int k = 0; k < 10; k++) s += sm[t + 32*k];
    #pragma unroll
    for (int o = 16; o > 0; o >>= 1) s += __shfl_down_sync(0xffffffffu, s, o);
    if (t == 0) sm[0] = s;
  }
  __syncthreads();
  double r = sm[0];
  __syncthreads();
  return r;
}

// K12: fused conv-W + conv-H of labels for one (b, d, h-half) tile (fp16 smem),
// plus per-batch partial sums of p, x, x*p. Last block computes class means.
__global__ void __launch_bounds__(320, 5) k12_convwh(const float* __restrict__ lab,
                                                     const float* __restrict__ inp){
  __shared__ __half raw[88][168];  // rows h0-4 .. h0+83, cols padded +4 each side
  __shared__ double sred[320];
  __shared__ int islast;
  int tid = threadIdx.x;
  int w = tid % 160, sub = tid / 160;     // sub in {0,1}
  int bid = blockIdx.x;
  int b  = bid / 320;                     // batch-major for mean pass
  int rem = bid - b * 320;
  int d  = rem >> 1;
  int hh = rem & 1;
  int h0 = hh * 80;
  const float* labp = lab + b * VOX + d * SS;
  const float* inpp = inp + b * VOX + d * SS;

  // zero left/right column pads (88 rows x 8 pad cols)
  for (int i = tid; i < 88 * 8; i += 320){
    int r = i >> 3, c8 = i & 7;
    int c = (c8 < 4) ? c8 : (160 + c8);
    raw[r][c] = __float2half(0.f);
  }

  // load 88 rows (2 per iteration across the 320 threads), fused sums over
  // the 80 interior rows
  float sp = 0.f, si = 0.f, sip = 0.f;
  #pragma unroll 4
  for (int k = 0; k < 44; k++){
    int r = 2 * k + sub;
    int h = h0 - 4 + r;
    float l = (h >= 0 && h < S) ? labp[h * S + w] : 0.f;
    raw[r][4 + w] = __float2half(l);
    if (r >= 4 && r < 84){
      float x = inpp[(h0 + r - 4) * S + w];
      sp += l; si += x; sip = fmaf(l, x, sip);
    }
  }
  __syncthreads();

  // rolling conv-H window over conv-W rows; thread (w, sub) outputs
  // h = h0 + sub*40 + j, j = 0..39  (local window rows sub*40+j .. +8)
  float win[9];
  #pragma unroll
  for (int i = 0; i < 9; i++){
    float a = 0.f;
    #pragma unroll
    for (int t = 0; t < 9; t++) a = fmaf(KW[t], __half2float(raw[sub*40 + i][w + t]), a);
    win[i] = a;
  }
  __half* dst = g_t2 + b * VOX + d * SS + w;
  #pragma unroll 4
  for (int j = 0; j < 40; j++){
    float acc = 0.f;
    #pragma unroll
    for (int i = 0; i < 9; i++) acc = fmaf(KW[i], win[i], acc);
    dst[(h0 + sub*40 + j) * S] = __float2half_rn(acc);
    #pragma unroll
    for (int i = 0; i < 8; i++) win[i] = win[i + 1];
    float a = 0.f;
    #pragma unroll
    for (int t = 0; t < 9; t++) a = fmaf(KW[t], __half2float(raw[sub*40 + j + 9][w + t]), a);
    win[8] = a;
  }

  double rp  = blockReduce320((double)sp,  sred);
  double ri  = blockReduce320((double)si,  sred);
  double rip = blockReduce320((double)sip, sred);
  if (tid == 0){
    g_p1[bid][0] = rp;
    g_p1[bid][1] = ri;
    g_p1[bid][2] = rip;
    __threadfence();
    unsigned int t = atomicAdd(&g_cnt12, 1u);
    islast = (t == NB12 - 1);
  }
  __syncthreads();
  if (islast){
    for (int bb = 0; bb < BATCH; bb++){
      double ap  = g_p1[bb*320 + tid][0];
      double ai  = g_p1[bb*320 + tid][1];
      double aip = g_p1[bb*320 + tid][2];
      ap  = blockReduce320(ap,  sred);
      ai  = blockReduce320(ai,  sred);
      aip = blockReduce320(aip, sred);
      if (tid == 0){
        double m0 = aip / (ap + 1e-5 * (double)VOX);
        double m1 = (ai - aip) / ((double)VOX - ap + 1e-5 * (double)VOX);
        g_mean[0][bb] = (float)m0;
        g_mean[1][bb] = (float)m1;
      }
    }
    if (tid == 0) g_cnt12 = 0;   // reset for next graph replay
  }
}

// K3: conv along D fused with the weighted reduction; each thread covers TWO
// w-columns via float2/half2 loads. G1 = closed-form conv3d(ones) - G0.
// Last block reduces g_p3 and writes the final scalar.
__global__ void __launch_bounds__(160, 8) k3_convd_reduce(const float* __restrict__ lab,
                                                          const float* __restrict__ inp,
                                                          float* __restrict__ out){
  __shared__ double sred[160];
  __shared__ int islast;
  int tid = threadIdx.x;
  int hh = tid / 80, w2 = tid % 80;
  int w = 2 * w2;
  int bid = blockIdx.x;
  int chunk = bid & 3;
  int r2 = bid >> 2;
  int b = r2 / 80, hp = r2 - b * 80;
  int h = 2 * hp + hh;
  int base = b * VOX + h * S + w;            // even
  const __half2* srcp = (const __half2*)(g_t2 + base);
  const float2*  labp = (const float2*)lab + (base >> 1);
  const float2*  inpp = (const float2*)inp + (base >> 1);
  float m0 = g_mean[0][b], m1 = g_mean[1][b];
  float se_h = esum(h);
  float sehx = se_h * esum(w);
  float sehy = se_h * esum(w + 1);
  int d0 = chunk * 40;

  float2 win[9];
  #pragma unroll
  for (int i = 0; i < 9; i++){
    int d = d0 - 4 + i;
    win[i] = (d >= 0 && d < S) ? __half22float2(srcp[d * (SS/2)])
                               : make_float2(0.f, 0.f);
  }
  float n0 = 0.f, dn0 = 0.f, n1 = 0.f, dn1 = 0.f;
  #pragma unroll 4
  for (int it = 0; it < 40; it++){
    int d = d0 + it;
    float g0x = 0.f, g0y = 0.f;
    #pragma unroll
    for (int k = 0; k < 9; k++){
      g0x = fmaf(KW[k], win[k].x, g0x);
      g0y = fmaf(KW[k], win[k].y, g0y);
    }
    float esd = esum(d);
    float g1x = fmaf(esd, sehx, -g0x);
    float g1y = fmaf(esd, sehy, -g0y);
    float2 l = labp[d * (SS/2)];
    float2 x = inpp[d * (SS/2)];
    // component x
    float q0 = (x.x - m0) * (x.x - m0);
    float q1 = (x.x - m1) * (x.x - m1);
    float w0 = __expf(-q0 * q0);
    float w1 = __expf(-q1 * q1);
    float t0 = w0 * g0x, t1 = w1 * g1x;
    n0  = fmaf(l.x, t0, n0);        dn0 += t0;
    n1  = fmaf(1.f - l.x, t1, n1);  dn1 += t1;
    // component y
    q0 = (x.y - m0) * (x.y - m0);
    q1 = (x.y - m1) * (x.y - m1);
    w0 = __expf(-q0 * q0);
    w1 = __expf(-q1 * q1);
    t0 = w0 * g0y; t1 = w1 * g1y;
    n0  = fmaf(l.y, t0, n0);        dn0 += t0;
    n1  = fmaf(1.f - l.y, t1, n1);  dn1 += t1;
    // roll window
    #pragma unroll
    for (int k = 0; k < 8; k++) win[k] = win[k + 1];
    int nd = d + 5;
    win[8] = (nd < S) ? __half22float2(srcp[nd * (SS/2)]) : make_float2(0.f, 0.f);
  }
  double r0 = blockReduce160((double)n0,  sred);
  double r1 = blockReduce160((double)dn0, sred);
  double r2d = blockReduce160((double)n1,  sred);
  double r3 = blockReduce160((double)dn1, sred);
  if (tid == 0){
    g_p3[bid][0] = r0;  g_p3[bid][1] = r1;
    g_p3[bid][2] = r2d; g_p3[bid][3] = r3;
    __threadfence();
    unsigned int t = atomicAdd(&g_cnt3, 1u);
    islast = (t == NB3 - 1);
  }
  __syncthreads();
  if (islast){
    double a0 = 0, a1 = 0, a2 = 0, a3 = 0;
    #pragma unroll
    for (int i = 0; i < 8; i++){
      int idx = tid + 160 * i;
      a0 += g_p3[idx][0]; a1 += g_p3[idx][1];
      a2 += g_p3[idx][2]; a3 += g_p3[idx][3];
    }
    a0 = blockReduce160(a0, sred);
    a1 = blockReduce160(a1, sred);
    a2 = blockReduce160(a2, sred);
    a3 = blockReduce160(a3, sred);
    if (tid == 0){
      double loss = fabs(a0 / (a1 + 1e-6)) + fabs(a2 / (a3 + 1e-6));
      out[0] = (float)(2.0 - loss);
      g_cnt3 = 0;   // reset for next graph replay
    }
  }
}

extern "C" void kernel_launch(void* const* d_in, const int* in_sizes, int n_in,
                              void* d_out, int out_size){
  const float* lab = (const float*)d_in[0];   // labels
  const float* inp = (const float*)d_in[1];   // inputs
  k12_convwh<<<NB12, 320>>>(lab, inp);
  k3_convd_reduce<<<NB3, 160>>>(lab, inp, (float*)d_out);
}

// round 10
// speedup vs baseline: 1.1504x; 1.1504x over previous
#include <cuda_runtime.h>
#include <cuda_fp16.h>
#include <math.h>

#define BATCH 4
#define S 160
#define SS (S*S)
#define VOX (S*S*S)
#define TOT (BATCH*VOX)

#define NB12 2560  // 4 chunks x (4 batch x 160 d-planes)
#define NB3  2560  // 4 chunks x (4 batch x 160 h-planes)

// 1D Gaussian taps exp(-t^2/50), t=-4..4
__constant__ float KW[9] = {
  0.72614902f, 0.83527023f, 0.92311633f, 0.98019868f, 1.0f,
  0.98019868f, 0.92311633f, 0.83527023f, 0.72614902f
};
#define KSUM1 7.92946854f
// prefix sums of first n taps (for edge-clipped kernel sums)
__constant__ float KPRE[5] = {0.f, 0.72614902f, 1.56141925f, 2.48453558f, 3.46473426f};

__device__ __half  g_t2[TOT];          // conv-W-H of labels (fp16)
__device__ double  g_p1[NB12][3];      // per-block partials: p, x, x*p
__device__ float   g_mean[2][BATCH];   // class means
__device__ double  g_p3[NB3][4];       // per-block partials: n0, d0, n1, d1
__device__ unsigned int g_cnt12;       // zero-init; reset by last block
__device__ unsigned int g_cnt3;

__device__ __forceinline__ float esum(int c){
  int lo = 4 - c;   if (lo < 0) lo = 0;
  int hi = c - 155; if (hi < 0) hi = 0;
  return KSUM1 - KPRE[lo] - KPRE[hi];
}

__device__ __forceinline__ double blockReduce160(double v, double* sm){
  int t = threadIdx.x;
  sm[t] = v;
  __syncthreads();
  if (t < 32){
    double s = sm[t] + sm[t+32] + sm[t+64] + sm[t+96] + sm[t+128];
    #pragma unroll
    for (int o = 16; o > 0; o >>= 1) s += __shfl_down_sync(0xffffffffu, s, o);
    if (t == 0) sm[0] = s;
  }
  __syncthreads();
  double r = sm[0];
  __syncthreads();
  return r;
}

// K12: fused conv-W + conv-H of labels for one (b, d, h-chunk) tile,
// plus per-batch partial sums of p, x, x*p. Last block computes class means.
__global__ void __launch_bounds__(160) k12_convwh(const float* __restrict__ lab,
                                                  const float* __restrict__ inp){
  __shared__ float raw[48][168];   // rows h0-4 .. h0+43, cols padded +4 each side
  __shared__ double sred[S];
  __shared__ int islast;
  int w = threadIdx.x;
  int bid = blockIdx.x;
  int chunk = bid & 3;
  int db = bid >> 2;               // b-major: bids [b*640,(b+1)*640) belong to batch b
  int b = db / S, d = db - b * S;
  int h0 = chunk * 40;
  const float* labp = lab + b * VOX + d * SS;
  const float* inpp = inp + b * VOX + d * SS;

  if (w < 8){
    int c = (w < 4) ? w : (160 + w);
    #pragma unroll 4
    for (int r = 0; r < 48; r++) raw[r][c] = 0.f;
  }

  float sp = 0.f, si = 0.f, sip = 0.f;
  #pragma unroll 8
  for (int r = 0; r < 48; r++){
    int h = h0 - 4 + r;
    float l = (h >= 0 && h < S) ? labp[h * S + w] : 0.f;
    raw[r][4 + w] = l;
    if (r >= 4 && r < 44){
      float x = inpp[(h0 + r - 4) * S + w];
      sp += l; si += x; sip = fmaf(l, x, sip);
    }
  }
  __syncthreads();

  float win[9];
  #pragma unroll
  for (int i = 0; i < 9; i++){
    float a = 0.f;
    #pragma unroll
    for (int t = 0; t < 9; t++) a = fmaf(KW[t], raw[i][w + t], a);
    win[i] = a;
  }
  __half* dst = g_t2 + b * VOX + d * SS + h0 * S + w;
  #pragma unroll 4
  for (int j = 0; j < 40; j++){
    float acc = 0.f;
    #pragma unroll
    for (int i = 0; i < 9; i++) acc = fmaf(KW[i], win[i], acc);
    dst[j * S] = __float2half_rn(acc);
    #pragma unroll
    for (int i = 0; i < 8; i++) win[i] = win[i + 1];
    float a = 0.f;
    #pragma unroll
    for (int t = 0; t < 9; t++) a = fmaf(KW[t], raw[j + 9][w + t], a);
    win[8] = a;
  }

  double rp  = blockReduce160((double)sp,  sred);
  double ri  = blockReduce160((double)si,  sred);
  double rip = blockReduce160((double)sip, sred);
  if (w == 0){
    g_p1[bid][0] = rp;
    g_p1[bid][1] = ri;
    g_p1[bid][2] = rip;
    __threadfence();
    unsigned int t = atomicAdd(&g_cnt12, 1u);
    islast = (t == NB12 - 1);
  }
  __syncthreads();
  if (islast){
    for (int bb = 0; bb < BATCH; bb++){
      double ap = 0, ai = 0, aip = 0;
      for (int i = w; i < 640; i += 160){
        ap  += g_p1[bb*640 + i][0];
        ai  += g_p1[bb*640 + i][1];
        aip += g_p1[bb*640 + i][2];
      }
      ap  = blockReduce160(ap,  sred);
      ai  = blockReduce160(ai,  sred);
      aip = blockReduce160(aip, sred);
      if (w == 0){
        double m0 = aip / (ap + 1e-5 * (double)VOX);
        double m1 = (ai - aip) / ((double)VOX - ap + 1e-5 * (double)VOX);
        g_mean[0][bb] = (float)m0;
        g_mean[1][bb] = (float)m1;
      }
    }
    if (w == 0) g_cnt12 = 0;   // reset for next graph replay
  }
}

// K3: conv along D (R1-style rolling window, one load per stream per iter)
// fused with the weighted reduction. G1 = closed-form conv3d(ones) - G0.
// Last block reduces g_p3 and writes the final scalar.
__global__ void __launch_bounds__(160, 8) k3_convd_reduce(const float* __restrict__ lab,
                                                          const float* __restrict__ inp,
                                                          float* __restrict__ out){
  __shared__ double sred[S];
  __shared__ int islast;
  int w = threadIdx.x;
  int bid = blockIdx.x;
  int chunk = bid & 3;
  int bh = bid >> 2;            // (b,h) plane
  int b = bh / S, h = bh - b * S;
  int base = b * VOX + h * S + w;
  const __half* src = g_t2 + base;
  float m0 = g_mean[0][b], m1 = g_mean[1][b];
  float se_hw = esum(h) * esum(w);
  int d0 = chunk * 40;
  float win[9];
  #pragma unroll
  for (int i = 0; i < 9; i++){
    int d = d0 - 4 + i;
    win[i] = (d >= 0 && d < S) ? __half2float(src[d * SS]) : 0.f;
  }
  float n0 = 0.f, dn0 = 0.f, n1 = 0.f, dn1 = 0.f;
  #pragma unroll 2
  for (int it = 0; it < 40; it++){
    int d = d0 + it;
    float G0 = 0.f;
    #pragma unroll
    for (int i = 0; i < 9; i++) G0 = fmaf(KW[i], win[i], G0);
    float G1 = fmaf(esum(d), se_hw, -G0);    // conv(1s) - conv(p0)
    int off = base + d * SS;
    float l = lab[off];
    float x = inp[off];
    float q0 = (x - m0) * (x - m0);
    float q1 = (x - m1) * (x - m1);
    float w0 = __expf(-q0 * q0);             // exp(-(diff)^2 / sigma2^2), sigma2=1
    float w1 = __expf(-q1 * q1);
    float t0 = w0 * G0, t1 = w1 * G1;
    n0  = fmaf(l, t0, n0);        dn0 += t0;
    n1  = fmaf(1.f - l, t1, n1);  dn1 += t1;
    #pragma unroll
    for (int i = 0; i < 8; i++) win[i] = win[i + 1];
    int nd = d + 5;
    win[8] = (nd < S) ? __half2float(src[nd * SS]) : 0.f;
  }
  double r0 = blockReduce160((double)n0,  sred);
  double r1 = blockReduce160((double)dn0, sred);
  double r2 = blockReduce160((double)n1,  sred);
  double r3 = blockReduce160((double)dn1, sred);
  if (w == 0){
    g_p3[bid][0] = r0; g_p3[bid][1] = r1;
    g_p3[bid][2] = r2; g_p3[bid][3] = r3;
    __threadfence();
    unsigned int t = atomicAdd(&g_cnt3, 1u);
    islast = (t == NB3 - 1);
  }
  __syncthreads();
  if (islast){
    double a0 = 0, a1 = 0, a2 = 0, a3 = 0;
    for (int i = w; i < NB3; i += 160){
      a0 += g_p3[i][0]; a1 += g_p3[i][1];
      a2 += g_p3[i][2]; a3 += g_p3[i][3];
    }
    a0 = blockReduce160(a0, sred);
    a1 = blockReduce160(a1, sred);
    a2 = blockReduce160(a2, sred);
    a3 = blockReduce160(a3, sred);
    if (w == 0){
      double loss = fabs(a0 / (a1 + 1e-6)) + fabs(a2 / (a3 + 1e-6));
      out[0] = (float)(2.0 - loss);
      g_cnt3 = 0;   // reset for next graph replay
    }
  }
}

extern "C" void kernel_launch(void* const* d_in, const int* in_sizes, int n_in,
                              void* d_out, int out_size){
  const float* lab = (const float*)d_in[0];   // labels
  const float* inp = (const float*)d_in[1];   // inputs
  k12_convwh<<<NB12, 160>>>(lab, inp);
  k3_convd_reduce<<<NB3, 160>>>(lab, inp, (float*)d_out);
}